// round 15
// baseline (speedup 1.0000x reference)
#include <cuda_runtime.h>

// Fixed problem shape: B=512, Np=128, Ng=128, TIME=5
#define BATCH 512
#define NP 128
#define NG 128
#define TSTEPS 5
#define NSEG 128                  // segments (one per gt vertex)
#define NPAIR (NSEG / 2)          // 64 packed segment pairs
#define NSLICE 4                  // slice lanes per pred (lanes 4q..4q+3)
#define ITERS (NPAIR / NSLICE)    // 16 pairs per thread (stride NSLICE)
#define PREDS_PER_CTA 64
#define CTA_THREADS 256           // 64 preds x 4 slice-lanes
#define NCTA (BATCH * (NP / PREDS_PER_CTA))  // 1024

__device__ float        g_partial[NCTA];
__device__ unsigned int g_count = 0;

// ---------- packed f32x2 helpers (sm_103a: add/mul/fma only) ----------
__device__ __forceinline__ unsigned long long pk2(float lo, float hi) {
    unsigned long long r;
    asm("mov.b64 %0, {%1, %2};" : "=l"(r) : "f"(lo), "f"(hi));
    return r;
}
__device__ __forceinline__ unsigned long long add2(unsigned long long a, unsigned long long b) {
    unsigned long long r;
    asm("add.rn.f32x2 %0, %1, %2;" : "=l"(r) : "l"(a), "l"(b));
    return r;
}
__device__ __forceinline__ unsigned long long mul2(unsigned long long a, unsigned long long b) {
    unsigned long long r;
    asm("mul.rn.f32x2 %0, %1, %2;" : "=l"(r) : "l"(a), "l"(b));
    return r;
}
__device__ __forceinline__ unsigned long long fma2(unsigned long long a, unsigned long long b,
                                                   unsigned long long c) {
    unsigned long long r;
    asm("fma.rn.f32x2 %0, %1, %2, %3;" : "=l"(r) : "l"(a), "l"(b), "l"(c));
    return r;
}

__device__ __forceinline__ float smooth_l1_elem(float d) {
    d = fabsf(d);
    return (d < 1.0f) ? (0.5f * d * d) : (d - 0.5f);
}

#define RMAGIC 12582912.0f        // 1.5 * 2^23
#define RMAGIC_BITS 0x4B400000    // float bits of RMAGIC
// bits(u + RMAGIC) == RMAGIC_BITS + round(u) as int (|u| << 2^21), so
// int-clamping the bits to [RMAGIC_BITS, RMAGIC_BITS+4] yields RMAGIC + k.

// Two CTAs per batch (64 preds each). Lanes 4q..4q+3 of each warp all own
// pred q and scan interleaved pair subsets t = 4j+sl — the slice combine is
// two shfl.bfly ops, no smem, no extra barrier, no serial section.
__global__ void __launch_bounds__(CTA_THREADS, 8)
dm_fused(const float2* __restrict__ pred,
         const float2* __restrict__ gt,
         float* __restrict__ out) {
    __shared__ __align__(16) float2 gtv[NG];   // raw gt vertices (1 KB)
    // Per-segment analytic data, packed for f32x2 pair processing (pair t):
    // A4[t] = {-ax[2t], -ax[2t+1], -ay[2t], -ay[2t+1]}
    // D4[t] = {dpx[2t], dpx[2t+1], dpy[2t], dpy[2t+1]}   dp  = -0.4*d (= -2d/5)
    // Q4[t] = {qq[2t],  qq[2t+1],  d2s[2t], d2s[2t+1]}   qq = -12.5/d2, d2s = d2/25
    __shared__ __align__(16) float A4[NPAIR * 4];
    __shared__ __align__(16) float D4[NPAIR * 4];
    __shared__ __align__(16) float Q4[NPAIR * 4];
    __shared__ float s_warp[8];
    __shared__ int   s_is_last;

    const int cta  = blockIdx.x;
    const int b    = cta >> 1;
    const int half = cta & 1;
    const int tid  = threadIdx.x;
    const int q    = tid >> 2;      // pred id within CTA
    const int sl   = tid & 3;       // slice lane 0..3
    const float2* gtb = gt + b * NG;

    // Build per-segment analytic data (one thread per segment).
    if (tid < NSEG) {
        int n = tid;
        float2 c = __ldg(&gtb[n]);
        float2 a = __ldg(&gtb[(n + NG - 1) & (NG - 1)]);
        gtv[n] = c;
        float dx = c.x - a.x, dy = c.y - a.y;
        float d2 = dx * dx + dy * dy;
        int pr = n >> 1, pa = n & 1;
        A4[4 * pr + pa]     = -a.x;
        A4[4 * pr + 2 + pa] = -a.y;
        D4[4 * pr + pa]     = -0.4f * dx;
        D4[4 * pr + 2 + pa] = -0.4f * dy;
        Q4[4 * pr + pa]     = -12.5f / d2;
        Q4[4 * pr + 2 + pa] = d2 * 0.04f;
    }
    __syncthreads();

    const float2 pp = pred[b * NP + half * PREDS_PER_CTA + q];
    const unsigned long long px2   = pk2(pp.x, pp.x);
    const unsigned long long py2   = pk2(pp.y, pp.y);
    const unsigned long long MAG2  = pk2(RMAGIC, RMAGIC);
    const unsigned long long NMAG2 = pk2(-RMAGIC, -RMAGIC);

    // Key: (analytic_min_dist_bits & 0xFFFFFF80) | t  (t = pair id, 0..63).
    unsigned int accE = 0xFFFFFFFFu, accO = 0xFFFFFFFFu;

    const ulonglong2* A2v = reinterpret_cast<const ulonglong2*>(A4);
    const ulonglong2* D2v = reinterpret_cast<const ulonglong2*>(D4);
    const ulonglong2* Q2v = reinterpret_cast<const ulonglong2*>(Q4);

    #pragma unroll 8
    for (unsigned int j = 0; j < ITERS; ++j) {
        const unsigned int t = 4u * j + (unsigned int)sl;  // this lane's pair
        ulonglong2 av = A2v[t];  // (-ax pair, -ay pair)
        ulonglong2 dv = D2v[t];  // (dp.x pair, dp.y pair)
        ulonglong2 qv = Q2v[t];  // (qq pair, d2/25 pair)
        unsigned long long ex2 = add2(px2, av.x);                  // e = p - a
        unsigned long long ey2 = add2(py2, av.y);
        unsigned long long dm2 = fma2(ey2, dv.y, mul2(ex2, dv.x)); // dm' = -2 e.d/5
        unsigned long long e22 = fma2(ey2, ey2, mul2(ex2, ex2));   // |e|^2
        unsigned long long r2m = fma2(dm2, qv.x, MAG2);            // u + MAGIC (fused)
        // int-domain clamp on magic bits (alu pipe): RMAGIC + clamp(round(u),0,4)
        int rb0 = (int)(unsigned int)r2m;
        int rb1 = (int)(unsigned int)(r2m >> 32);
        rb0 = min(max(rb0, RMAGIC_BITS), RMAGIC_BITS + 4);
        rb1 = min(max(rb1, RMAGIC_BITS), RMAGIC_BITS + 4);
        unsigned long long km2 = pk2(__int_as_float(rb0), __int_as_float(rb1));
        unsigned long long kf2 = add2(km2, NMAG2);                 // kf = clamped k
        unsigned long long Dd2 = fma2(kf2, fma2(kf2, qv.y, dm2), e22);
        accE = min(accE, (((unsigned int)Dd2)         & 0xFFFFFF80u) | t);
        accO = min(accO, (((unsigned int)(Dd2 >> 32)) & 0xFFFFFF80u) | t);
    }
    // Rebuild: segment index n = 2t (+1 for odd) in 8 low bits; D bits >= 8.
    unsigned int keyE = (accE & 0xFFFFFF00u) | ((accE & 0x7Fu) << 1);
    unsigned int keyO = (accO & 0xFFFFFF00u) | ((accO & 0x7Fu) << 1) | 1u;
    unsigned int best = min(keyE, keyO);
    // Combine the 4 slice lanes of this pred (lanes 4q..4q+3): 2 butterflies.
    best = min(best, __shfl_xor_sync(0xFFFFFFFFu, best, 1));
    best = min(best, __shfl_xor_sync(0xFFFFFFFFu, best, 2));

    // All 4 lanes compute the identical epilogue (redundant but barrier-free).
    int n  = (int)(best & 0xFFu);
    int pr = n >> 1, pa = n & 1;
    float ex = pp.x + A4[4 * pr + pa];
    float ey = pp.y + A4[4 * pr + 2 + pa];
    float dm = fmaf(ey, D4[4 * pr + 2 + pa], ex * D4[4 * pr + pa]);
    float rm = fmaf(dm, Q4[4 * pr + pa], RMAGIC);
    int   rb = min(max(__float_as_int(rm), RMAGIC_BITS), RMAGIC_BITS + 4);
    float kf = __int_as_float(rb) - RMAGIC;
    float s  = kf * 0.2f;                 // == t/5 in fp32 for k = 0..4
    float2 c = gtv[n];
    float2 a = gtv[(n + NG - 1) & (NG - 1)];
    float mx = c.x * s + a.x * (1.0f - s);   // exact reference formula
    float my = c.y * s + a.y * (1.0f - s);
    float l = smooth_l1_elem(pp.x - mx) + smooth_l1_elem(pp.y - my);
    l = (sl == 0) ? l : 0.0f;             // count each pred once
    // Deterministic warp butterfly: sums the warp's 8 preds.
    #pragma unroll
    for (int o = 16; o > 0; o >>= 1)
        l += __shfl_xor_sync(0xFFFFFFFFu, l, o);
    if ((tid & 31) == 0) s_warp[tid >> 5] = l;
    __syncthreads();

    if (tid == 0) {
        float csum = ((s_warp[0] + s_warp[1]) + (s_warp[2] + s_warp[3]))
                   + ((s_warp[4] + s_warp[5]) + (s_warp[6] + s_warp[7]));
        g_partial[cta] = csum;
        __threadfence();
        unsigned int old = atomicAdd(&g_count, 1u);
        s_is_last = (old == (unsigned int)(gridDim.x - 1));
    }
    __syncthreads();

    if (s_is_last && tid < 32) {
        __threadfence();
        // Single-warp deterministic final reduction: fixed per-lane order,
        // fixed butterfly. 32 back-to-back L2 loads per lane (MLP-covered).
        float ssum = 0.0f;
        #pragma unroll
        for (int i = 0; i < 32; ++i)
            ssum += __ldcg(&g_partial[tid + 32 * i]);
        #pragma unroll
        for (int o = 16; o > 0; o >>= 1)
            ssum += __shfl_xor_sync(0xFFFFFFFFu, ssum, o);
        if (tid == 0) {
            out[0] = ssum * (1.0f / (float)(BATCH * NP * 2));
            g_count = 0;   // reset for next graph replay
        }
    }
}

extern "C" void kernel_launch(void* const* d_in, const int* in_sizes, int n_in,
                              void* d_out, int out_size) {
    const float2* pred = (const float2*)d_in[1];
    const float2* gt   = (const float2*)d_in[2];
    dm_fused<<<NCTA, CTA_THREADS>>>(pred, gt, (float*)d_out);
}

// round 16
// speedup vs baseline: 1.0614x; 1.0614x over previous
#include <cuda_runtime.h>

// Fixed problem shape: B=512, Np=128, Ng=128, TIME=5
#define BATCH 512
#define NP 128
#define NG 128
#define TSTEPS 5
#define NSEG 128                  // segments (one per gt vertex)
#define NSLICE 4                  // segment slices per pred
#define SEGS_PER_SLICE (NSEG / NSLICE)       // 32
#define PAIRS_PER_SLICE (SEGS_PER_SLICE / 2) // 16
#define PREDS_PER_CTA 64
#define CTA_THREADS 256           // 64 preds x 4 slices
#define NCTA (BATCH * (NP / PREDS_PER_CTA))  // 1024

__device__ float        g_partial[NCTA];
__device__ unsigned int g_count = 0;

// ---------- packed f32x2 helpers (sm_103a: add/mul/fma only) ----------
__device__ __forceinline__ unsigned long long pk2(float lo, float hi) {
    unsigned long long r;
    asm("mov.b64 %0, {%1, %2};" : "=l"(r) : "f"(lo), "f"(hi));
    return r;
}
__device__ __forceinline__ unsigned long long add2(unsigned long long a, unsigned long long b) {
    unsigned long long r;
    asm("add.rn.f32x2 %0, %1, %2;" : "=l"(r) : "l"(a), "l"(b));
    return r;
}
__device__ __forceinline__ unsigned long long mul2(unsigned long long a, unsigned long long b) {
    unsigned long long r;
    asm("mul.rn.f32x2 %0, %1, %2;" : "=l"(r) : "l"(a), "l"(b));
    return r;
}
__device__ __forceinline__ unsigned long long fma2(unsigned long long a, unsigned long long b,
                                                   unsigned long long c) {
    unsigned long long r;
    asm("fma.rn.f32x2 %0, %1, %2, %3;" : "=l"(r) : "l"(a), "l"(b), "l"(c));
    return r;
}
__device__ __forceinline__ float lo2(unsigned long long v) {
    return __uint_as_float((unsigned int)v);
}
__device__ __forceinline__ float hi2(unsigned long long v) {
    return __uint_as_float((unsigned int)(v >> 32));
}

__device__ __forceinline__ float smooth_l1_elem(float d) {
    d = fabsf(d);
    return (d < 1.0f) ? (0.5f * d * d) : (d - 0.5f);
}

#define RMAGIC 12582912.0f   // 1.5 * 2^23: (x+RMAGIC)-RMAGIC = round-to-nearest int

// Two CTAs per batch (64 preds each). Thread (sl = tid>>6, q = tid&63) scans
// segment slice [32*sl, 32*sl+32) analytically; broadcast LDS (all lanes of a
// warp read the same table address). TWO independent pair-streams (t, t+8)
// per loop iteration break the dependency chain (software pipelining).
__global__ void __launch_bounds__(CTA_THREADS, 7)
dm_fused(const float2* __restrict__ pred,
         const float2* __restrict__ gt,
         float* __restrict__ out) {
    __shared__ __align__(16) float2 gtv[NG];   // raw gt vertices (1 KB)
    // Per-segment analytic data, packed for f32x2 pair processing (pair t):
    // A4[t] = {-ax[2t], -ax[2t+1], -ay[2t], -ay[2t+1]}
    // D4[t] = {dpx[2t], dpx[2t+1], dpy[2t], dpy[2t+1]}   dp  = -0.4*d (= -2d/5)
    // Q4[t] = {qq[2t],  qq[2t+1],  d2s[2t], d2s[2t+1]}   qq = -12.5/d2, d2s = d2/25
    __shared__ __align__(16) float A4[NSEG / 2 * 4];
    __shared__ __align__(16) float D4[NSEG / 2 * 4];
    __shared__ __align__(16) float Q4[NSEG / 2 * 4];
    __shared__ unsigned int s_amin[NSLICE][PREDS_PER_CTA];
    __shared__ float s_warp[2];
    __shared__ int   s_is_last;

    const int cta  = blockIdx.x;
    const int b    = cta >> 1;
    const int half = cta & 1;
    const int tid  = threadIdx.x;
    const int q    = tid & 63;      // pred id within CTA
    const int sl   = tid >> 6;      // slice id 0..3
    const float2* gtb = gt + b * NG;

    // Build per-segment analytic data (one thread per segment).
    if (tid < NSEG) {
        int n = tid;
        float2 c = __ldg(&gtb[n]);
        float2 a = __ldg(&gtb[(n + NG - 1) & (NG - 1)]);
        gtv[n] = c;
        float dx = c.x - a.x, dy = c.y - a.y;
        float d2 = dx * dx + dy * dy;
        int pr = n >> 1, pa = n & 1;
        A4[4 * pr + pa]     = -a.x;
        A4[4 * pr + 2 + pa] = -a.y;
        D4[4 * pr + pa]     = -0.4f * dx;
        D4[4 * pr + 2 + pa] = -0.4f * dy;
        Q4[4 * pr + pa]     = -12.5f / d2;
        Q4[4 * pr + 2 + pa] = d2 * 0.04f;
    }
    __syncthreads();

    const float2 pp = pred[b * NP + half * PREDS_PER_CTA + q];
    const unsigned long long px2   = pk2(pp.x, pp.x);
    const unsigned long long py2   = pk2(pp.y, pp.y);
    const unsigned long long MAG2  = pk2(RMAGIC, RMAGIC);
    const unsigned long long NMAG2 = pk2(-RMAGIC, -RMAGIC);

    // Key: (analytic_min_dist_bits & 0xFFFFFF80) | j  (j = local pair, 0..15).
    unsigned int aE0 = 0xFFFFFFFFu, aO0 = 0xFFFFFFFFu;   // stream 0: j
    unsigned int aE1 = 0xFFFFFFFFu, aO1 = 0xFFFFFFFFu;   // stream 1: j+8

    const int pair0 = sl * PAIRS_PER_SLICE;
    const ulonglong2* A2v = reinterpret_cast<const ulonglong2*>(A4) + pair0;
    const ulonglong2* D2v = reinterpret_cast<const ulonglong2*>(D4) + pair0;
    const ulonglong2* Q2v = reinterpret_cast<const ulonglong2*>(Q4) + pair0;

    #pragma unroll
    for (unsigned int j = 0; j < PAIRS_PER_SLICE / 2; ++j) {
        // ---- stream 0: pair j ----
        ulonglong2 av0 = A2v[j];
        ulonglong2 dv0 = D2v[j];
        ulonglong2 qv0 = Q2v[j];
        // ---- stream 1: pair j+8 ----
        ulonglong2 av1 = A2v[j + 8];
        ulonglong2 dv1 = D2v[j + 8];
        ulonglong2 qv1 = Q2v[j + 8];

        unsigned long long ex0 = add2(px2, av0.x);
        unsigned long long ey0 = add2(py2, av0.y);
        unsigned long long ex1 = add2(px2, av1.x);
        unsigned long long ey1 = add2(py2, av1.y);

        unsigned long long dm0 = fma2(ey0, dv0.y, mul2(ex0, dv0.x));
        unsigned long long dm1 = fma2(ey1, dv1.y, mul2(ex1, dv1.x));
        unsigned long long e20 = fma2(ey0, ey0, mul2(ex0, ex0));
        unsigned long long e21 = fma2(ey1, ey1, mul2(ex1, ex1));

        unsigned long long rm0 = fma2(dm0, qv0.x, MAG2);   // u + MAGIC (fused)
        unsigned long long rm1 = fma2(dm1, qv1.x, MAG2);
        unsigned long long r0  = add2(rm0, NMAG2);         // round(u)
        unsigned long long r1  = add2(rm1, NMAG2);

        // scalar clamp (NaN from degenerate d2=0 clamps to 0 via fmaxf)
        float k00 = fminf(fmaxf(lo2(r0), 0.0f), 4.0f);
        float k01 = fminf(fmaxf(hi2(r0), 0.0f), 4.0f);
        float k10 = fminf(fmaxf(lo2(r1), 0.0f), 4.0f);
        float k11 = fminf(fmaxf(hi2(r1), 0.0f), 4.0f);
        unsigned long long kf0 = pk2(k00, k01);
        unsigned long long kf1 = pk2(k10, k11);

        unsigned long long Dd0 = fma2(kf0, fma2(kf0, qv0.y, dm0), e20);
        unsigned long long Dd1 = fma2(kf1, fma2(kf1, qv1.y, dm1), e21);

        aE0 = min(aE0, (((unsigned int)Dd0)         & 0xFFFFFF80u) | j);
        aO0 = min(aO0, (((unsigned int)(Dd0 >> 32)) & 0xFFFFFF80u) | j);
        aE1 = min(aE1, (((unsigned int)Dd1)         & 0xFFFFFF80u) | (j + 8u));
        aO1 = min(aO1, (((unsigned int)(Dd1 >> 32)) & 0xFFFFFF80u) | (j + 8u));
    }
    // Merge streams (same key format; smaller j wins ties = first occurrence).
    unsigned int accE = min(aE0, aE1);
    unsigned int accO = min(aO0, aO1);
    // Rebuild keys with global segment index n (7 bits) in the low field.
    const unsigned int base0 = (unsigned int)(sl * SEGS_PER_SLICE);
    unsigned int keyE = (accE & 0xFFFFFF80u) | (base0 + ((accE & 0x7Fu) << 1));
    unsigned int keyO = (accO & 0xFFFFFF80u) | (base0 + ((accO & 0x7Fu) << 1) + 1u);
    s_amin[sl][q] = min(keyE, keyO);
    __syncthreads();

    if (tid < PREDS_PER_CTA) {   // q == tid, pp is this pred point
        unsigned int best = min(min(s_amin[0][tid], s_amin[1][tid]),
                                min(s_amin[2][tid], s_amin[3][tid]));
        int n  = (int)(best & 0x7Fu);
        int pr = n >> 1, pa = n & 1;
        // recompute kf for the winning segment (same fused formula as the loop)
        float ex = pp.x + A4[4 * pr + pa];
        float ey = pp.y + A4[4 * pr + 2 + pa];
        float dm = fmaf(ey, D4[4 * pr + 2 + pa], ex * D4[4 * pr + pa]);
        float rm = fmaf(dm, Q4[4 * pr + pa], RMAGIC);
        float kf = fminf(fmaxf(rm - RMAGIC, 0.0f), 4.0f);
        float s  = kf * 0.2f;                 // == t/5 in fp32 for k = 0..4
        float2 c = gtv[n];
        float2 a = gtv[(n + NG - 1) & (NG - 1)];
        float mx = c.x * s + a.x * (1.0f - s);   // exact reference formula
        float my = c.y * s + a.y * (1.0f - s);
        float l = smooth_l1_elem(pp.x - mx) + smooth_l1_elem(pp.y - my);
        #pragma unroll
        for (int o = 16; o > 0; o >>= 1)
            l += __shfl_xor_sync(0xFFFFFFFFu, l, o);
        if ((tid & 31) == 0) s_warp[tid >> 5] = l;
    }
    __syncthreads();

    if (tid == 0) {
        g_partial[cta] = s_warp[0] + s_warp[1];
        __threadfence();
        unsigned int old = atomicAdd(&g_count, 1u);
        s_is_last = (old == (unsigned int)(gridDim.x - 1));
    }
    __syncthreads();

    if (s_is_last && tid < 32) {
        __threadfence();
        // Single-warp deterministic final reduction: fixed per-lane order,
        // fixed butterfly. 32 back-to-back L2 loads per lane (MLP-covered).
        float ssum = 0.0f;
        #pragma unroll
        for (int i = 0; i < 32; ++i)
            ssum += __ldcg(&g_partial[tid + 32 * i]);
        #pragma unroll
        for (int o = 16; o > 0; o >>= 1)
            ssum += __shfl_xor_sync(0xFFFFFFFFu, ssum, o);
        if (tid == 0) {
            out[0] = ssum * (1.0f / (float)(BATCH * NP * 2));
            g_count = 0;   // reset for next graph replay
        }
    }
}

extern "C" void kernel_launch(void* const* d_in, const int* in_sizes, int n_in,
                              void* d_out, int out_size) {
    const float2* pred = (const float2*)d_in[1];
    const float2* gt   = (const float2*)d_in[2];
    dm_fused<<<NCTA, CTA_THREADS>>>(pred, gt, (float*)d_out);
}

// round 17
// speedup vs baseline: 1.0800x; 1.0175x over previous
#include <cuda_runtime.h>

// Fixed problem shape: B=512, Np=128, Ng=128, TIME=5
#define BATCH 512
#define NP 128
#define NG 128
#define TSTEPS 5
#define NSEG 128                  // segments (one per gt vertex)
#define NPAIR (NSEG / 2)          // 64 packed segment pairs
#define NSLICE 8                  // one slice per warp (8 pairs each)
#define PAIRS_PER_SLICE (NPAIR / NSLICE)   // 8
#define PREDS_PER_CTA 64          // 32 duos x 2
#define CTA_THREADS 256           // 8 warps x 32 lanes
#define NCTA (BATCH * (NP / PREDS_PER_CTA))  // 1024

__device__ float        g_partial[NCTA];
__device__ unsigned int g_count = 0;

// ---------- packed f32x2 helpers (sm_103a: add/mul/fma only) ----------
__device__ __forceinline__ unsigned long long pk2(float lo, float hi) {
    unsigned long long r;
    asm("mov.b64 %0, {%1, %2};" : "=l"(r) : "f"(lo), "f"(hi));
    return r;
}
__device__ __forceinline__ unsigned long long add2(unsigned long long a, unsigned long long b) {
    unsigned long long r;
    asm("add.rn.f32x2 %0, %1, %2;" : "=l"(r) : "l"(a), "l"(b));
    return r;
}
__device__ __forceinline__ unsigned long long mul2(unsigned long long a, unsigned long long b) {
    unsigned long long r;
    asm("mul.rn.f32x2 %0, %1, %2;" : "=l"(r) : "l"(a), "l"(b));
    return r;
}
__device__ __forceinline__ unsigned long long fma2(unsigned long long a, unsigned long long b,
                                                   unsigned long long c) {
    unsigned long long r;
    asm("fma.rn.f32x2 %0, %1, %2, %3;" : "=l"(r) : "l"(a), "l"(b), "l"(c));
    return r;
}

__device__ __forceinline__ float smooth_l1_elem(float d) {
    d = fabsf(d);
    return (d < 1.0f) ? (0.5f * d * d) : (d - 0.5f);
}

#define RMAGIC 12582912.0f        // 1.5 * 2^23
#define RMAGIC_BITS 0x4B400000    // float bits of RMAGIC
// bits(u + RMAGIC) == RMAGIC_BITS + round(u) as int (|u| << 2^21), so
// int-clamping the bits to [RMAGIC_BITS, RMAGIC_BITS+4] yields RMAGIC + k.

// Two CTAs per batch (64 preds each). Warp w owns segment pairs 8w..8w+7;
// lane owns preds 2*lane and 2*lane+1. Table addresses depend only on (w,j)
// -> every LDS.128 is a 32-lane broadcast, and each load serves TWO preds
// (halves the smem-crossbar traffic that matches the measured wall gap).
__global__ void __launch_bounds__(CTA_THREADS, 7)
dm_fused(const float2* __restrict__ pred,
         const float2* __restrict__ gt,
         float* __restrict__ out) {
    __shared__ __align__(16) float2 gtv[NG];   // raw gt vertices (1 KB)
    // Per-segment analytic data, packed for f32x2 pair processing (pair t):
    // A4[t] = {-ax[2t], -ax[2t+1], -ay[2t], -ay[2t+1]}
    // D4[t] = {dpx[2t], dpx[2t+1], dpy[2t], dpy[2t+1]}   dp  = -0.4*d (= -2d/5)
    // Q4[t] = {qq[2t],  qq[2t+1],  d2s[2t], d2s[2t+1]}   qq = -12.5/d2, d2s = d2/25
    __shared__ __align__(16) float A4[NPAIR * 4];
    __shared__ __align__(16) float D4[NPAIR * 4];
    __shared__ __align__(16) float Q4[NPAIR * 4];
    __shared__ unsigned int s_amin[NSLICE][PREDS_PER_CTA];
    __shared__ float s_warp[2];
    __shared__ int   s_is_last;

    const int cta  = blockIdx.x;
    const int b    = cta >> 1;
    const int half = cta & 1;
    const int tid  = threadIdx.x;
    const int lane = tid & 31;      // pred-duo id
    const int w    = tid >> 5;      // slice id 0..7
    const float2* gtb = gt + b * NG;

    // Build per-segment analytic data (one thread per segment).
    if (tid < NSEG) {
        int n = tid;
        float2 c = __ldg(&gtb[n]);
        float2 a = __ldg(&gtb[(n + NG - 1) & (NG - 1)]);
        gtv[n] = c;
        float dx = c.x - a.x, dy = c.y - a.y;
        float d2 = dx * dx + dy * dy;
        int pr = n >> 1, pa = n & 1;
        A4[4 * pr + pa]     = -a.x;
        A4[4 * pr + 2 + pa] = -a.y;
        D4[4 * pr + pa]     = -0.4f * dx;
        D4[4 * pr + 2 + pa] = -0.4f * dy;
        Q4[4 * pr + pa]     = -12.5f / d2;
        Q4[4 * pr + 2 + pa] = d2 * 0.04f;
    }
    __syncthreads();

    const int pbase = b * NP + half * PREDS_PER_CTA;
    const float2 pA = pred[pbase + 2 * lane + 0];
    const float2 pB = pred[pbase + 2 * lane + 1];
    const unsigned long long pxA = pk2(pA.x, pA.x), pyA = pk2(pA.y, pA.y);
    const unsigned long long pxB = pk2(pB.x, pB.x), pyB = pk2(pB.y, pB.y);
    const unsigned long long MAG2  = pk2(RMAGIC, RMAGIC);
    const unsigned long long NMAG2 = pk2(-RMAGIC, -RMAGIC);

    // Key: (analytic_min_dist_bits & 0xFFFFFF80) | j  (j = local pair, 0..7).
    unsigned int aEA = 0xFFFFFFFFu, aOA = 0xFFFFFFFFu;
    unsigned int aEB = 0xFFFFFFFFu, aOB = 0xFFFFFFFFu;

    const int pair0 = w * PAIRS_PER_SLICE;
    const ulonglong2* A2v = reinterpret_cast<const ulonglong2*>(A4) + pair0;
    const ulonglong2* D2v = reinterpret_cast<const ulonglong2*>(D4) + pair0;
    const ulonglong2* Q2v = reinterpret_cast<const ulonglong2*>(Q4) + pair0;

    #pragma unroll
    for (unsigned int j = 0; j < PAIRS_PER_SLICE; ++j) {
        ulonglong2 av = A2v[j];  // broadcast: all 32 lanes same address
        ulonglong2 dv = D2v[j];
        ulonglong2 qv = Q2v[j];
        // ---- pred A ----
        {
            unsigned long long ex2 = add2(pxA, av.x);
            unsigned long long ey2 = add2(pyA, av.y);
            unsigned long long dm2 = fma2(ey2, dv.y, mul2(ex2, dv.x));
            unsigned long long e22 = fma2(ey2, ey2, mul2(ex2, ex2));
            unsigned long long r2m = fma2(dm2, qv.x, MAG2);
            int rb0 = (int)(unsigned int)r2m;
            int rb1 = (int)(unsigned int)(r2m >> 32);
            rb0 = min(max(rb0, RMAGIC_BITS), RMAGIC_BITS + 4);
            rb1 = min(max(rb1, RMAGIC_BITS), RMAGIC_BITS + 4);
            unsigned long long kf2 = add2(pk2(__int_as_float(rb0),
                                              __int_as_float(rb1)), NMAG2);
            unsigned long long Dd2 = fma2(kf2, fma2(kf2, qv.y, dm2), e22);
            aEA = min(aEA, (((unsigned int)Dd2)         & 0xFFFFFF80u) | j);
            aOA = min(aOA, (((unsigned int)(Dd2 >> 32)) & 0xFFFFFF80u) | j);
        }
        // ---- pred B ----
        {
            unsigned long long ex2 = add2(pxB, av.x);
            unsigned long long ey2 = add2(pyB, av.y);
            unsigned long long dm2 = fma2(ey2, dv.y, mul2(ex2, dv.x));
            unsigned long long e22 = fma2(ey2, ey2, mul2(ex2, ex2));
            unsigned long long r2m = fma2(dm2, qv.x, MAG2);
            int rb0 = (int)(unsigned int)r2m;
            int rb1 = (int)(unsigned int)(r2m >> 32);
            rb0 = min(max(rb0, RMAGIC_BITS), RMAGIC_BITS + 4);
            rb1 = min(max(rb1, RMAGIC_BITS), RMAGIC_BITS + 4);
            unsigned long long kf2 = add2(pk2(__int_as_float(rb0),
                                              __int_as_float(rb1)), NMAG2);
            unsigned long long Dd2 = fma2(kf2, fma2(kf2, qv.y, dm2), e22);
            aEB = min(aEB, (((unsigned int)Dd2)         & 0xFFFFFF80u) | j);
            aOB = min(aOB, (((unsigned int)(Dd2 >> 32)) & 0xFFFFFF80u) | j);
        }
    }
    // Rebuild: local segment = (j<<1)|pa (4 bits); global n = 16w + local.
    const unsigned int nbase = (unsigned int)(16 * w);
    {
        unsigned int kE = (aEA & 0xFFFFFF80u) | (nbase + ((aEA & 0x7Fu) << 1));
        unsigned int kO = (aOA & 0xFFFFFF80u) | (nbase + ((aOA & 0x7Fu) << 1) + 1u);
        s_amin[w][2 * lane + 0] = min(kE, kO);
    }
    {
        unsigned int kE = (aEB & 0xFFFFFF80u) | (nbase + ((aEB & 0x7Fu) << 1));
        unsigned int kO = (aOB & 0xFFFFFF80u) | (nbase + ((aOB & 0x7Fu) << 1) + 1u);
        s_amin[w][2 * lane + 1] = min(kE, kO);
    }
    __syncthreads();

    if (tid < PREDS_PER_CTA) {   // one thread per pred point
        unsigned int best = min(min(min(s_amin[0][tid], s_amin[1][tid]),
                                    min(s_amin[2][tid], s_amin[3][tid])),
                                min(min(s_amin[4][tid], s_amin[5][tid]),
                                    min(s_amin[6][tid], s_amin[7][tid])));
        int n  = (int)(best & 0x7Fu);
        int pr = n >> 1, pa = n & 1;
        float2 pp = __ldg(&pred[pbase + tid]);
        // recompute kf for the winning segment (same int-clamp formula)
        float ex = pp.x + A4[4 * pr + pa];
        float ey = pp.y + A4[4 * pr + 2 + pa];
        float dm = fmaf(ey, D4[4 * pr + 2 + pa], ex * D4[4 * pr + pa]);
        float rm = fmaf(dm, Q4[4 * pr + pa], RMAGIC);
        int   rb = min(max(__float_as_int(rm), RMAGIC_BITS), RMAGIC_BITS + 4);
        float kf = __int_as_float(rb) - RMAGIC;
        float s  = kf * 0.2f;                 // == t/5 in fp32 for k = 0..4
        float2 c = gtv[n];
        float2 a = gtv[(n + NG - 1) & (NG - 1)];
        float mx = c.x * s + a.x * (1.0f - s);   // exact reference formula
        float my = c.y * s + a.y * (1.0f - s);
        float l = smooth_l1_elem(pp.x - mx) + smooth_l1_elem(pp.y - my);
        #pragma unroll
        for (int o = 16; o > 0; o >>= 1)
            l += __shfl_xor_sync(0xFFFFFFFFu, l, o);
        if ((tid & 31) == 0) s_warp[tid >> 5] = l;
    }
    __syncthreads();

    if (tid == 0) {
        g_partial[cta] = s_warp[0] + s_warp[1];
        __threadfence();
        unsigned int old = atomicAdd(&g_count, 1u);
        s_is_last = (old == (unsigned int)(gridDim.x - 1));
    }
    __syncthreads();

    if (s_is_last && tid < 32) {
        __threadfence();
        // Single-warp deterministic final reduction: fixed per-lane order,
        // fixed butterfly. 32 back-to-back L2 loads per lane (MLP-covered).
        float ssum = 0.0f;
        #pragma unroll
        for (int i = 0; i < 32; ++i)
            ssum += __ldcg(&g_partial[tid + 32 * i]);
        #pragma unroll
        for (int o = 16; o > 0; o >>= 1)
            ssum += __shfl_xor_sync(0xFFFFFFFFu, ssum, o);
        if (tid == 0) {
            out[0] = ssum * (1.0f / (float)(BATCH * NP * 2));
            g_count = 0;   // reset for next graph replay
        }
    }
}

extern "C" void kernel_launch(void* const* d_in, const int* in_sizes, int n_in,
                              void* d_out, int out_size) {
    const float2* pred = (const float2*)d_in[1];
    const float2* gt   = (const float2*)d_in[2];
    dm_fused<<<NCTA, CTA_THREADS>>>(pred, gt, (float*)d_out);
}